// round 3
// baseline (speedup 1.0000x reference)
#include <cuda_runtime.h>

// PoseODE: y' = MLP(y), y0 = 0, batch-invariant -> single 768-vector trajectory.
// 512 sequential matvec stages executed by a persistent grid with a custom
// grid-wide barrier. Weights cached in SMEM (6 columns per CTA, 128 CTAs).

#define F      768
#define GRID_G 128
#define RPC    6     // output columns per CTA (128*6 = 768)
#define T      192   // 6 warps, warp w owns column c0+w
#define NSTEP  64

__device__ float g_ybuf[2][F];
__device__ float g_h[F];
__device__ float g_k[4][F];
__device__ float g_r1[128];
__device__ float g_r2[256];
__device__ float g_r3[128];
__device__ float g_pose[6];
__device__ unsigned g_arrive = 0;
__device__ unsigned g_epoch  = 0;

__device__ __forceinline__ float4 ldcg4(const float* p) {
    return __ldcg((const float4*)p);
}

// Sense-free monotonic-epoch grid barrier. Self-resetting (g_arrive returns to
// 0 every use, so graph replays are safe). Every thread reads the epoch BEFORE
// the internal __syncthreads (so no thread can capture a post-release epoch),
// and every thread polls (in-order warp issue => loads after the poll are an
// acquire for L1-bypassing __ldcg reads).
__device__ __forceinline__ void grid_barrier() {
    unsigned e = *(volatile unsigned*)&g_epoch;
    __threadfence();            // release: prior __stcg stores visible at L2
    __syncthreads();
    if (threadIdx.x == 0) {
        if (atomicAdd(&g_arrive, 1u) == GRID_G - 1u) {
            *(volatile unsigned*)&g_arrive = 0u;
            __threadfence();
            *(volatile unsigned*)&g_epoch = e + 1u;
        }
    }
    while (*(volatile unsigned*)&g_epoch == e) { }
}

__device__ __forceinline__ float warp_dot(const float* vsm, const float* wrow, int lane) {
    float acc = 0.0f;
#pragma unroll
    for (int k = 0; k < 6; k++) {
        int i = k * 128 + lane * 4;
        float4 a = *(const float4*)(vsm + i);
        float4 b = *(const float4*)(wrow + i);
        acc = fmaf(a.x, b.x, acc);
        acc = fmaf(a.y, b.y, acc);
        acc = fmaf(a.z, b.z, acc);
        acc = fmaf(a.w, b.w, acc);
    }
#pragma unroll
    for (int o = 16; o; o >>= 1) acc += __shfl_xor_sync(0xffffffffu, acc, o);
    return acc;   // valid on lane 0
}

// Block-wide dot of SMEM vector src[0..L) with column `col` of row-major
// weight wmat[L][outF], + bias. Result valid on thread 0 only.
__device__ __forceinline__ float block_dot(const float* src, int L,
                                           const float* wmat, int outF, int col,
                                           const float* bias, float* red) {
    int tid = threadIdx.x, warp = tid >> 5, lane = tid & 31;
    float p = 0.0f;
    for (int i = tid; i < L; i += T) p = fmaf(src[i], __ldg(&wmat[i * outF + col]), p);
#pragma unroll
    for (int o = 16; o; o >>= 1) p += __shfl_xor_sync(0xffffffffu, p, o);
    if (lane == 0) red[warp] = p;
    __syncthreads();
    float s = 0.0f;
    if (tid == 0) {
        for (int w = 0; w < 6; w++) s += red[w];
        s += __ldg(&bias[col]);
    }
    __syncthreads();
    return s;
}

__device__ __forceinline__ float lrelu(float x) { return x > 0.0f ? x : 0.1f * x; }

__global__ __launch_bounds__(T, 1) void pose_ode_kernel(
    const float* __restrict__ ts,
    const float* __restrict__ w1, const float* __restrict__ b1,
    const float* __restrict__ w2, const float* __restrict__ b2,
    const float* __restrict__ rw1, const float* __restrict__ rb1,
    const float* __restrict__ rw2, const float* __restrict__ rb2,
    const float* __restrict__ rw3, const float* __restrict__ rb3,
    const float* __restrict__ rw4, const float* __restrict__ rb4,
    float* __restrict__ out, int out_n)
{
    __shared__ float w1s[RPC * F];   // 18 KB: columns c0..c0+5 of ode_w1
    __shared__ float w2s[RPC * F];   // 18 KB
    __shared__ float vsm[F];         // 3 KB : stage input vector
    __shared__ float red[8];
    __shared__ float pose_s[6];

    const int tid  = threadIdx.x;
    const int warp = tid >> 5;
    const int lane = tid & 31;
    const int c0   = blockIdx.x * RPC;
    const int j    = c0 + warp;      // this warp's output column

    // ---- one-time: gather this CTA's weight columns into SMEM (coalesced) ----
    for (int idx = tid; idx < RPC * F; idx += T) {
        int i = idx / RPC;
        int r = idx - i * RPC;
        w1s[r * F + i] = w1[i * F + c0 + r];
        w2s[r * F + i] = w2[i * F + c0 + r];
    }

    // ---- zero initial state (re-done every replay; deterministic) ----
    if (blockIdx.x == 0) {
        float4 z = make_float4(0.f, 0.f, 0.f, 0.f);
        __stcg(((float4*)g_ybuf[0]) + tid, z);   // T == F/4 exactly
    }
    grid_barrier();

    // ---- 64 RK4(3/8) steps, 8 grid-synced matvec stages per step ----
    int cur = 0;
#pragma unroll 1
    for (int s = 0; s < NSTEP; s++) {
        const float dt  = __ldg(&ts[s + 1]) - __ldg(&ts[s]);
        const float dt3 = dt * (1.0f / 3.0f);
        const float* y  = g_ybuf[cur];
        const int i4 = tid * 4;

#pragma unroll 1
        for (int e = 0; e < 4; e++) {
            // build v = y + combo(k1,k2,k3) into SMEM
            float4 v = ldcg4(y + i4);
            if (e == 1) {
                float4 a = ldcg4(g_k[0] + i4);
                v.x += dt3 * a.x; v.y += dt3 * a.y; v.z += dt3 * a.z; v.w += dt3 * a.w;
            } else if (e == 2) {
                float4 a = ldcg4(g_k[0] + i4);
                float4 b = ldcg4(g_k[1] + i4);
                v.x += dt * b.x - dt3 * a.x; v.y += dt * b.y - dt3 * a.y;
                v.z += dt * b.z - dt3 * a.z; v.w += dt * b.w - dt3 * a.w;
            } else if (e == 3) {
                float4 a = ldcg4(g_k[0] + i4);
                float4 b = ldcg4(g_k[1] + i4);
                float4 c = ldcg4(g_k[2] + i4);
                v.x += dt * (a.x - b.x + c.x); v.y += dt * (a.y - b.y + c.y);
                v.z += dt * (a.z - b.z + c.z); v.w += dt * (a.w - b.w + c.w);
            }
            ((float4*)vsm)[tid] = v;
            __syncthreads();

            // stage 1: h = tanh(v @ W1 + b1)
            float acc = warp_dot(vsm, w1s + warp * F, lane);
            if (lane == 0) __stcg(&g_h[j], tanhf(acc + __ldg(&b1[j])));
            grid_barrier();

            // stage 2: k_e = h @ W2 + b2
            ((float4*)vsm)[tid] = ldcg4(g_h + i4);
            __syncthreads();
            float acc2 = warp_dot(vsm, w2s + warp * F, lane);
            if (lane == 0) {
                float kv = acc2 + __ldg(&b2[j]);
                __stcg(&g_k[e][j], kv);
                if (e == 3) {
                    float yj = __ldcg(&y[j]);
                    float k1 = __ldcg(&g_k[0][j]);
                    float k2 = __ldcg(&g_k[1][j]);
                    float k3 = __ldcg(&g_k[2][j]);
                    __stcg(&g_ybuf[cur ^ 1][j],
                           yj + dt * 0.125f * (k1 + 3.0f * (k2 + k3) + kv));
                }
            }
            grid_barrier();
        }
        cur ^= 1;
    }
    // after 64 steps (even), yT lives in g_ybuf[0]

    // ---- regressor: 768 -> 128 -> 256 -> 128 -> 6 ----
    ((float4*)vsm)[tid] = ldcg4(g_ybuf[0] + tid * 4);
    __syncthreads();
    float o1 = block_dot(vsm, 768, rw1, 128, blockIdx.x, rb1, red);
    if (tid == 0) __stcg(&g_r1[blockIdx.x], lrelu(o1));
    grid_barrier();

    if (tid < 32) ((float4*)vsm)[tid] = ldcg4(g_r1 + tid * 4);
    __syncthreads();
    float o2a = block_dot(vsm, 128, rw2, 256, blockIdx.x,       rb2, red);
    float o2b = block_dot(vsm, 128, rw2, 256, blockIdx.x + 128, rb2, red);
    if (tid == 0) {
        __stcg(&g_r2[blockIdx.x],       lrelu(o2a));
        __stcg(&g_r2[blockIdx.x + 128], lrelu(o2b));
    }
    grid_barrier();

    if (tid < 64) ((float4*)vsm)[tid] = ldcg4(g_r2 + tid * 4);
    __syncthreads();
    float o3 = block_dot(vsm, 256, rw3, 128, blockIdx.x, rb3, red);
    if (tid == 0) __stcg(&g_r3[blockIdx.x], lrelu(o3));
    grid_barrier();

    if (tid < 32) ((float4*)vsm)[tid] = ldcg4(g_r3 + tid * 4);
    __syncthreads();
    int pc = blockIdx.x % 6;
    float o4 = block_dot(vsm, 128, rw4, 6, pc, rb4, red);
    if (tid == 0 && blockIdx.x < 6) __stcg(&g_pose[pc], o4);   // no activation
    grid_barrier();

    // ---- broadcast outputs: [pose (256*6) | yT (256*768)] ----
    ((float4*)vsm)[tid] = ldcg4(g_ybuf[0] + tid * 4);
    if (tid < 6) pose_s[tid] = __ldcg(&g_pose[tid]);
    __syncthreads();

    for (int idx = blockIdx.x * T + tid; idx < out_n; idx += GRID_G * T) {
        float val;
        if (idx < 1536) {
            val = pose_s[idx % 6];
        } else {
            val = vsm[(idx - 1536) % 768];
        }
        out[idx] = val;
    }
}

extern "C" void kernel_launch(void* const* d_in, const int* in_sizes, int n_in,
                              void* d_out, int out_size) {
    // input order: fv, fv_alter, fi, dec (unused), ts, ode_w1, ode_b1, ode_w2,
    // ode_b2, reg_w1, reg_b1, reg_w2, reg_b2, reg_w3, reg_b3, reg_w4, reg_b4
    const float* ts  = (const float*)d_in[4];
    const float* w1  = (const float*)d_in[5];
    const float* b1  = (const float*)d_in[6];
    const float* w2  = (const float*)d_in[7];
    const float* b2  = (const float*)d_in[8];
    const float* rw1 = (const float*)d_in[9];
    const float* rb1 = (const float*)d_in[10];
    const float* rw2 = (const float*)d_in[11];
    const float* rb2 = (const float*)d_in[12];
    const float* rw3 = (const float*)d_in[13];
    const float* rb3 = (const float*)d_in[14];
    const float* rw4 = (const float*)d_in[15];
    const float* rb4 = (const float*)d_in[16];

    pose_ode_kernel<<<GRID_G, T>>>(ts, w1, b1, w2, b2,
                                   rw1, rb1, rw2, rb2, rw3, rb3, rw4, rb4,
                                   (float*)d_out, out_size);
}

// round 4
// speedup vs baseline: 1.1526x; 1.1526x over previous
#include <cuda_runtime.h>

// PoseODE: y' = MLP(y), y0 = 0, batch-invariant -> single 768-vector trajectory.
// 512 sequential matvec stages. Cross-CTA exchange via fence-free tagged
// 8-byte {value,tag} slots (double-buffered), no grid barriers in the loop.

#define F      768
#define G      128   // CTAs
#define RPC    6     // columns per CTA (128*6 = 768)
#define T      192   // 6 warps; warp w owns column blockIdx.x*6 + w
#define NSTEP  64

__device__ uint2    g_x[2][F];      // {float bits, round tag}, double-buffered
__device__ unsigned g_arrive = 0;   // one-shot startup barrier
__device__ unsigned g_epoch  = 0;

// ---------------- fence-free tagged publish / wait ----------------
__device__ __forceinline__ void publish(uint2* slot, float v, unsigned tag) {
    asm volatile("st.global.cg.v2.u32 [%0], {%1,%2};"
                 :: "l"(slot), "r"(__float_as_uint(v)), "r"(tag) : "memory");
}

__device__ __forceinline__ float wait1(const uint2* slot, unsigned tag) {
    unsigned v, t;
    do {
        asm volatile("ld.global.cg.v2.u32 {%0,%1},[%2];"
                     : "=r"(v), "=r"(t) : "l"(slot));
    } while (t != tag);
    return __uint_as_float(v);
}

// Poll 4 consecutive slots together (MLP=4, ~1 L2 round trip when ready).
__device__ __forceinline__ void wait4(const uint2* base, unsigned tag, float* out) {
    unsigned v0,t0,v1,t1,v2,t2,v3,t3;
    do {
        asm volatile(
            "ld.global.cg.v2.u32 {%0,%1},[%8];\n\t"
            "ld.global.cg.v2.u32 {%2,%3},[%8+8];\n\t"
            "ld.global.cg.v2.u32 {%4,%5},[%8+16];\n\t"
            "ld.global.cg.v2.u32 {%6,%7},[%8+24];"
            : "=r"(v0),"=r"(t0),"=r"(v1),"=r"(t1),
              "=r"(v2),"=r"(t2),"=r"(v3),"=r"(t3)
            : "l"(base));
    } while ((t0 ^ tag) | (t1 ^ tag) | (t2 ^ tag) | (t3 ^ tag));
    out[0] = __uint_as_float(v0); out[1] = __uint_as_float(v1);
    out[2] = __uint_as_float(v2); out[3] = __uint_as_float(v3);
}

// ---------------- one-shot startup barrier (after tag zeroing) ----------------
__device__ __forceinline__ void grid_barrier_once() {
    unsigned e = *(volatile unsigned*)&g_epoch;
    __threadfence();
    __syncthreads();
    if (threadIdx.x == 0) {
        if (atomicAdd(&g_arrive, 1u) == G - 1u) {
            *(volatile unsigned*)&g_arrive = 0u;
            __threadfence();
            *(volatile unsigned*)&g_epoch = e + 1u;
        }
    }
    while (*(volatile unsigned*)&g_epoch == e) { }
}

// ---------------- compute helpers ----------------
__device__ __forceinline__ float warp_dot(const float* vsm, const float* wrow, int lane) {
    float acc = 0.0f;
#pragma unroll
    for (int k = 0; k < 6; k++) {
        int i = k * 128 + lane * 4;
        float4 a = *(const float4*)(vsm + i);
        float4 b = *(const float4*)(wrow + i);
        acc = fmaf(a.x, b.x, acc);
        acc = fmaf(a.y, b.y, acc);
        acc = fmaf(a.z, b.z, acc);
        acc = fmaf(a.w, b.w, acc);
    }
#pragma unroll
    for (int o = 16; o; o >>= 1) acc += __shfl_xor_sync(0xffffffffu, acc, o);
    return acc;   // valid on lane 0
}

__device__ __forceinline__ float block_dot(const float* src, int L,
                                           const float* wmat, int outF, int col,
                                           const float* bias, float* red) {
    int tid = threadIdx.x, warp = tid >> 5, lane = tid & 31;
    float p = 0.0f;
    for (int i = tid; i < L; i += T) p = fmaf(src[i], __ldg(&wmat[i * outF + col]), p);
#pragma unroll
    for (int o = 16; o; o >>= 1) p += __shfl_xor_sync(0xffffffffu, p, o);
    if (lane == 0) red[warp] = p;
    __syncthreads();
    float s = 0.0f;
    if (tid == 0) {
        for (int w = 0; w < 6; w++) s += red[w];
        s += __ldg(&bias[col]);
    }
    __syncthreads();
    return s;
}

__device__ __forceinline__ float lrelu(float x) { return x > 0.0f ? x : 0.1f * x; }

// One MLP eval: vsm already holds v (not yet synced). Publishes h then k_e,
// returns consumed k_e in kout (per-thread 4 elements). Two tagged rounds.
__device__ __forceinline__ void mlp_eval(float* vsm, float* hsm,
                                         const float* w1row, const float* w2row,
                                         float b1c, float b2c,
                                         int tid, int lane, int j,
                                         unsigned& t, float* kout)
{
    __syncthreads();                               // vsm complete; hsm free
    float a1 = warp_dot(vsm, w1row, lane);
    unsigned th = ++t;
    uint2* bh = g_x[th & 1];
    if (lane == 0) publish(&bh[j], tanhf(a1 + b1c), th);
    float hv[4];
    wait4(&bh[tid * 4], th, hv);
    ((float4*)hsm)[tid] = make_float4(hv[0], hv[1], hv[2], hv[3]);
    __syncthreads();                               // hsm complete
    float a2 = warp_dot(hsm, w2row, lane);
    unsigned tk = ++t;
    uint2* bk = g_x[tk & 1];
    if (lane == 0) publish(&bk[j], a2 + b2c, tk);
    wait4(&bk[tid * 4], tk, kout);
}

__global__ __launch_bounds__(T, 1) void pose_ode_kernel(
    const float* __restrict__ ts,
    const float* __restrict__ w1, const float* __restrict__ b1,
    const float* __restrict__ w2, const float* __restrict__ b2,
    const float* __restrict__ rw1, const float* __restrict__ rb1,
    const float* __restrict__ rw2, const float* __restrict__ rb2,
    const float* __restrict__ rw3, const float* __restrict__ rb3,
    const float* __restrict__ rw4, const float* __restrict__ rb4,
    float* __restrict__ out, int out_n)
{
    __shared__ float w1s[RPC * F];    // 18 KB
    __shared__ float w2s[RPC * F];    // 18 KB
    __shared__ float vsm[F];          // matvec-1 input
    __shared__ float hsm[F];          // matvec-2 input / regressor exchange
    __shared__ float ysm[F];          // final yT (kept for output)
    __shared__ float red[8];
    __shared__ float pose_s[8];
    __shared__ float dts[NSTEP];

    const int tid  = threadIdx.x;
    const int warp = tid >> 5;
    const int lane = tid & 31;
    const int bid  = blockIdx.x;
    const int c0   = bid * RPC;
    const int j    = c0 + warp;       // this warp's output column

    // ---- load this CTA's weight columns into SMEM ----
    for (int idx = tid; idx < RPC * F; idx += T) {
        int i = idx / RPC;
        int r = idx - i * RPC;
        w1s[r * F + i] = w1[i * F + c0 + r];
        w2s[r * F + i] = w2[i * F + c0 + r];
    }
    if (tid < NSTEP) dts[tid] = __ldg(&ts[tid + 1]) - __ldg(&ts[tid]);

    // ---- zero all exchange tags (fresh per replay), then one grid barrier ----
    {
        uint2* flat = (uint2*)g_x;
        for (int i = bid * T + tid; i < 2 * F; i += G * T)
            publish(&flat[i], 0.0f, 0u);
    }
    grid_barrier_once();   // includes __syncthreads -> SMEM ready too

    const float* w1row = w1s + warp * F;
    const float* w2row = w2s + warp * F;
    const float  b1c = b1[j];
    const float  b2c = b2[j];

    // ---- 64 RK4(3/8) steps; state in per-thread registers ----
    float yr[4] = {0.f, 0.f, 0.f, 0.f};
    float ynr[4], k1[4], k2[4], k3[4], k4[4];
    unsigned t = 0;
    const int i4 = tid * 4;

#pragma unroll 1
    for (int s = 0; s < NSTEP; s++) {
        const float dt  = dts[s];
        const float dt3 = dt * (1.0f / 3.0f);

#pragma unroll
        for (int q = 0; q < 4; q++) vsm[i4 + q] = yr[q];
        mlp_eval(vsm, hsm, w1row, w2row, b1c, b2c, tid, lane, j, t, k1);

#pragma unroll
        for (int q = 0; q < 4; q++) {
            ynr[q] = fmaf(dt * 0.125f, k1[q], yr[q]);
            vsm[i4 + q] = fmaf(dt3, k1[q], yr[q]);
        }
        mlp_eval(vsm, hsm, w1row, w2row, b1c, b2c, tid, lane, j, t, k2);

#pragma unroll
        for (int q = 0; q < 4; q++) {
            ynr[q] = fmaf(dt * 0.375f, k2[q], ynr[q]);
            vsm[i4 + q] = yr[q] + dt * k2[q] - dt3 * k1[q];
        }
        mlp_eval(vsm, hsm, w1row, w2row, b1c, b2c, tid, lane, j, t, k3);

#pragma unroll
        for (int q = 0; q < 4; q++) {
            ynr[q] = fmaf(dt * 0.375f, k3[q], ynr[q]);
            vsm[i4 + q] = yr[q] + dt * (k1[q] - k2[q] + k3[q]);
        }
        mlp_eval(vsm, hsm, w1row, w2row, b1c, b2c, tid, lane, j, t, k4);

#pragma unroll
        for (int q = 0; q < 4; q++) yr[q] = fmaf(dt * 0.125f, k4[q], ynr[q]);
    }

    // ---- final state to SMEM (kept for output) ----
    __syncthreads();   // all warps done with last hsm/vsm reads
#pragma unroll
    for (int q = 0; q < 4; q++) ysm[i4 + q] = yr[q];
    __syncthreads();

    // ---- regressor 768->128->256->128->6 via tagged rounds ----
    {
        float o1 = block_dot(ysm, 768, rw1, 128, bid, rb1, red);
        unsigned tr = ++t; uint2* b = g_x[tr & 1];
        if (tid == 0) publish(&b[bid], lrelu(o1), tr);
        if (tid < 128) hsm[tid] = wait1(&b[tid], tr);
        __syncthreads();

        float o2a = block_dot(hsm, 128, rw2, 256, bid,       rb2, red);
        float o2b = block_dot(hsm, 128, rw2, 256, bid + 128, rb2, red);
        tr = ++t; b = g_x[tr & 1];
        if (tid == 0) {
            publish(&b[bid],       lrelu(o2a), tr);
            publish(&b[bid + 128], lrelu(o2b), tr);
        }
        for (int i = tid; i < 256; i += T) hsm[i] = wait1(&b[i], tr);
        __syncthreads();

        float o3 = block_dot(hsm, 256, rw3, 128, bid, rb3, red);
        tr = ++t; b = g_x[tr & 1];
        if (tid == 0) publish(&b[bid], lrelu(o3), tr);
        if (tid < 128) hsm[tid] = wait1(&b[tid], tr);
        __syncthreads();

        float o4 = block_dot(hsm, 128, rw4, 6, bid % 6, rb4, red);
        tr = ++t; b = g_x[tr & 1];
        if (tid == 0 && bid < 6) publish(&b[bid], o4, tr);   // no activation
        if (tid < 6) pose_s[tid] = wait1(&b[tid], tr);
        __syncthreads();
    }

    // ---- outputs: [pose (256*6) | yT (256*768)] ----
    for (int idx = bid * T + tid; idx < out_n; idx += G * T) {
        out[idx] = (idx < 1536) ? pose_s[idx % 6] : ysm[(idx - 1536) % 768];
    }
}

extern "C" void kernel_launch(void* const* d_in, const int* in_sizes, int n_in,
                              void* d_out, int out_size) {
    // order: fv, fv_alter, fi, dec (unused), ts, ode_w1, ode_b1, ode_w2, ode_b2,
    // reg_w1, reg_b1, reg_w2, reg_b2, reg_w3, reg_b3, reg_w4, reg_b4
    const float* ts  = (const float*)d_in[4];
    const float* w1  = (const float*)d_in[5];
    const float* b1  = (const float*)d_in[6];
    const float* w2  = (const float*)d_in[7];
    const float* b2  = (const float*)d_in[8];
    const float* rw1 = (const float*)d_in[9];
    const float* rb1 = (const float*)d_in[10];
    const float* rw2 = (const float*)d_in[11];
    const float* rb2 = (const float*)d_in[12];
    const float* rw3 = (const float*)d_in[13];
    const float* rb3 = (const float*)d_in[14];
    const float* rw4 = (const float*)d_in[15];
    const float* rb4 = (const float*)d_in[16];

    pose_ode_kernel<<<G, T>>>(ts, w1, b1, w2, b2,
                              rw1, rb1, rw2, rb2, rw3, rb3, rw4, rb4,
                              (float*)d_out, out_size);
}

// round 5
// speedup vs baseline: 1.8165x; 1.5760x over previous
#include <cuda_runtime.h>

// PoseODE: y' = MLP(y), y0 = 0, batch-invariant -> single 768-vector trajectory.
// 512 sequential matvec stages. Cross-CTA exchange via self-validating 32-byte
// packets (two 16B tagged halves, STG.128-atomic) -- no fences, no barriers,
// no poll storm: 128 poller lanes per CTA, one packet each.

#define F      768
#define G      128   // CTAs
#define RPC    6     // columns per CTA (128*6 = 768); 6 vals + 2 tags = 32B packet
#define T      192   // 6 warps; warp w owns column blockIdx.x*6 + w
#define NSTEP  64

// packet: half0 = {tag, v0, v1, v2}, half1 = {v3, v4, v5, tag}
__device__ uint4 g_p[2][G][2] = {};   // double-buffered by round parity
__device__ uint2 g_s[2][256]  = {};   // tagged 8B slots for regressor rounds

static __device__ __forceinline__ uint4 ldcg_v4(const uint4* p) {
    uint4 r;
    asm volatile("ld.global.cg.v4.u32 {%0,%1,%2,%3},[%4];"
                 : "=r"(r.x), "=r"(r.y), "=r"(r.z), "=r"(r.w) : "l"(p));
    return r;
}
static __device__ __forceinline__ void stcg_v4(uint4* p, uint4 v) {
    asm volatile("st.global.cg.v4.u32 [%0],{%1,%2,%3,%4};"
                 :: "l"(p), "r"(v.x), "r"(v.y), "r"(v.z), "r"(v.w) : "memory");
}
static __device__ __forceinline__ void pub8(uint2* s, float v, unsigned tag) {
    asm volatile("st.global.cg.v2.u32 [%0],{%1,%2};"
                 :: "l"(s), "r"(__float_as_uint(v)), "r"(tag) : "memory");
}
static __device__ __forceinline__ float wait8(const uint2* s, unsigned tag) {
    unsigned v, t;
    do {
        asm volatile("ld.global.cg.v2.u32 {%0,%1},[%2];" : "=r"(v), "=r"(t) : "l"(s));
    } while (t != tag);
    return __uint_as_float(v);
}

static __device__ __forceinline__ float lrelu(float x) { return x > 0.0f ? x : 0.1f * x; }

// Block-wide dot of SMEM vector src[0..L) with column `col` of wmat[L][outF].
__device__ __forceinline__ float block_dot(const float* src, int L,
                                           const float* wmat, int outF, int col,
                                           const float* bias, volatile float* red) {
    int tid = threadIdx.x, warp = tid >> 5, lane = tid & 31;
    float p = 0.0f;
    for (int i = tid; i < L; i += T) p = fmaf(src[i], __ldg(&wmat[i * outF + col]), p);
#pragma unroll
    for (int o = 16; o; o >>= 1) p += __shfl_xor_sync(0xffffffffu, p, o);
    if (lane == 0) red[warp] = p;
    __syncthreads();
    float s = 0.0f;
    if (tid == 0) {
        for (int w = 0; w < 6; w++) s += red[w];
        s += __ldg(&bias[col]);
    }
    __syncthreads();
    return s;
}

// Publish this CTA's 6 values (in pack_s[0..5]) for round `rnd`, wait for all
// 128 CTAs' packets, scatter the full 768-vector into dst. pack_s must be
// complete (caller syncs before). Exits with dst complete + block synced.
__device__ __forceinline__ void exchange(const float* pack_s, float* dst,
                                         unsigned rnd, int bid, int tid) {
    if (tid == 0) {
        uint4 h0, h1;
        h0.x = rnd;
        h0.y = __float_as_uint(pack_s[0]);
        h0.z = __float_as_uint(pack_s[1]);
        h0.w = __float_as_uint(pack_s[2]);
        h1.x = __float_as_uint(pack_s[3]);
        h1.y = __float_as_uint(pack_s[4]);
        h1.z = __float_as_uint(pack_s[5]);
        h1.w = rnd;
        uint4* base = g_p[rnd & 1][bid];
        stcg_v4(base,     h0);
        stcg_v4(base + 1, h1);
    }
    if (tid < G) {
        const uint4* pp = g_p[rnd & 1][tid];
        uint4 a, c;
        do { a = ldcg_v4(pp); c = ldcg_v4(pp + 1); } while (a.x != rnd || c.w != rnd);
        float* d = dst + tid * 6;
        d[0] = __uint_as_float(a.y);
        d[1] = __uint_as_float(a.z);
        d[2] = __uint_as_float(a.w);
        d[3] = __uint_as_float(c.x);
        d[4] = __uint_as_float(c.y);
        d[5] = __uint_as_float(c.z);
    }
    __syncthreads();
}

__global__ __launch_bounds__(T, 1) void pose_ode_kernel(
    const float* __restrict__ ts,
    const float* __restrict__ w1, const float* __restrict__ b1,
    const float* __restrict__ w2, const float* __restrict__ b2,
    const float* __restrict__ rw1, const float* __restrict__ rb1,
    const float* __restrict__ rw2, const float* __restrict__ rb2,
    const float* __restrict__ rw3, const float* __restrict__ rb3,
    const float* __restrict__ rw4, const float* __restrict__ rb4,
    float* __restrict__ out, int out_n)
{
    __shared__ float4 vsm4[F / 4];       // stage input vector / final yT
    __shared__ float4 hsm4[F / 4];       // hidden vector
    __shared__ float4 ksm4[F / 4];       // k vector
    __shared__ float  wstage[RPC * F];   // 18 KB one-time weight staging
    __shared__ float  pack_s[8];
    __shared__ float  red[8];
    __shared__ float  pose_s[8];
    __shared__ float  dts[NSTEP];

    float* vsm = (float*)vsm4;
    float* hsm = (float*)hsm4;
    float* ksm = (float*)ksm4;

    const int tid  = threadIdx.x;
    const int warp = tid >> 5;
    const int lane = tid & 31;
    const int bid  = blockIdx.x;
    const int c0   = bid * RPC;
    const int j    = c0 + warp;          // this warp's output column

    if (tid < NSTEP) dts[tid] = __ldg(&ts[tid + 1]) - __ldg(&ts[tid]);

    // ---- stage weight columns into SMEM (coalesced), then into registers ----
    float4 w1r[6], w2r[6];
    for (int idx = tid; idx < RPC * F; idx += T) {
        int i = idx / RPC, r = idx - i * RPC;
        wstage[r * F + i] = w1[i * F + c0 + r];
    }
    __syncthreads();
#pragma unroll
    for (int k = 0; k < 6; k++)
        w1r[k] = ((const float4*)(wstage + warp * F))[k * 32 + lane];
    __syncthreads();
    for (int idx = tid; idx < RPC * F; idx += T) {
        int i = idx / RPC, r = idx - i * RPC;
        wstage[r * F + i] = w2[i * F + c0 + r];
    }
    __syncthreads();
#pragma unroll
    for (int k = 0; k < 6; k++)
        w2r[k] = ((const float4*)(wstage + warp * F))[k * 32 + lane];

    const float b1c = __ldg(&b1[j]);
    const float b2c = __ldg(&b2[j]);

    // ---- initial state: y0 = 0 ----
    vsm4[tid] = make_float4(0.f, 0.f, 0.f, 0.f);    // T == F/4
    __syncthreads();

    float yr[4]  = {0.f, 0.f, 0.f, 0.f};
    float ynr[4], k1r[4], k2r[4], k3r[4];
    unsigned rnd = 0;

#pragma unroll 1
    for (int s = 0; s < NSTEP; s++) {
        const float dt  = dts[s];
        const float dt3 = dt * (1.0f / 3.0f);

#pragma unroll 1
        for (int e = 0; e < 4; e++) {
            // ---- layer 1: h = tanh(v @ W1 + b1), column j by warp `warp` ----
            float acc = 0.0f;
#pragma unroll
            for (int k = 0; k < 6; k++) {
                float4 a = vsm4[k * 32 + lane];
                acc = fmaf(a.x, w1r[k].x, acc);
                acc = fmaf(a.y, w1r[k].y, acc);
                acc = fmaf(a.z, w1r[k].z, acc);
                acc = fmaf(a.w, w1r[k].w, acc);
            }
#pragma unroll
            for (int o = 16; o; o >>= 1) acc += __shfl_xor_sync(0xffffffffu, acc, o);
            if (lane == 0) pack_s[warp] = tanhf(acc + b1c);
            __syncthreads();
            exchange(pack_s, hsm, ++rnd, bid, tid);

            // ---- layer 2: k_e = h @ W2 + b2 ----
            float acc2 = 0.0f;
#pragma unroll
            for (int k = 0; k < 6; k++) {
                float4 a = hsm4[k * 32 + lane];
                acc2 = fmaf(a.x, w2r[k].x, acc2);
                acc2 = fmaf(a.y, w2r[k].y, acc2);
                acc2 = fmaf(a.z, w2r[k].z, acc2);
                acc2 = fmaf(a.w, w2r[k].w, acc2);
            }
#pragma unroll
            for (int o = 16; o; o >>= 1) acc2 += __shfl_xor_sync(0xffffffffu, acc2, o);
            if (lane == 0) pack_s[warp] = acc2 + b2c;
            __syncthreads();
            exchange(pack_s, ksm, ++rnd, bid, tid);

            // ---- per-thread state update (owns elements 4*tid .. 4*tid+3) ----
            float4 kq = ksm4[tid];
            float kv[4] = {kq.x, kq.y, kq.z, kq.w};
            float vv[4];
            if (e == 0) {
#pragma unroll
                for (int q = 0; q < 4; q++) {
                    k1r[q] = kv[q];
                    ynr[q] = fmaf(dt * 0.125f, kv[q], yr[q]);
                    vv[q]  = fmaf(dt3, kv[q], yr[q]);
                }
            } else if (e == 1) {
#pragma unroll
                for (int q = 0; q < 4; q++) {
                    k2r[q] = kv[q];
                    ynr[q] = fmaf(dt * 0.375f, kv[q], ynr[q]);
                    vv[q]  = yr[q] + dt * kv[q] - dt3 * k1r[q];
                }
            } else if (e == 2) {
#pragma unroll
                for (int q = 0; q < 4; q++) {
                    k3r[q] = kv[q];
                    ynr[q] = fmaf(dt * 0.375f, kv[q], ynr[q]);
                    vv[q]  = yr[q] + dt * (k1r[q] - k2r[q] + kv[q]);
                }
            } else {
#pragma unroll
                for (int q = 0; q < 4; q++) {
                    yr[q] = fmaf(dt * 0.125f, kv[q], ynr[q]);
                    vv[q] = yr[q];
                }
            }
            vsm4[tid] = make_float4(vv[0], vv[1], vv[2], vv[3]);
            __syncthreads();
        }
    }
    // vsm now holds yT (and is not modified below).

    // ---- regressor 768->128->256->128->6 via tagged 8B rounds ----
    {
        float o1 = block_dot(vsm, 768, rw1, 128, bid, rb1, red);
        unsigned tr = ++rnd; uint2* b = g_s[tr & 1];
        if (tid == 0) pub8(&b[bid], lrelu(o1), tr);
        if (tid < 128) hsm[tid] = wait8(&b[tid], tr);
        __syncthreads();

        float o2a = block_dot(hsm, 128, rw2, 256, bid,       rb2, red);
        float o2b = block_dot(hsm, 128, rw2, 256, bid + 128, rb2, red);
        tr = ++rnd; b = g_s[tr & 1];
        if (tid == 0) {
            pub8(&b[bid],       lrelu(o2a), tr);
            pub8(&b[bid + 128], lrelu(o2b), tr);
        }
        for (int i = tid; i < 256; i += T) hsm[i] = wait8(&b[i], tr);
        __syncthreads();

        float o3 = block_dot(hsm, 256, rw3, 128, bid, rb3, red);
        tr = ++rnd; b = g_s[tr & 1];
        if (tid == 0) pub8(&b[bid], lrelu(o3), tr);
        if (tid < 128) ksm[tid] = wait8(&b[tid], tr);
        __syncthreads();

        float o4 = block_dot(ksm, 128, rw4, 6, bid % 6, rb4, red);
        tr = ++rnd; b = g_s[tr & 1];
        if (tid == 0 && bid < 6) pub8(&b[bid], o4, tr);   // no activation
        if (tid < 6) pose_s[tid] = wait8(&b[tid], tr);
        __syncthreads();
    }

    // ---- outputs: [pose (256*6) | yT (256*768)] ----
    for (int idx = bid * T + tid; idx < out_n; idx += G * T) {
        out[idx] = (idx < 1536) ? pose_s[idx % 6] : vsm[(idx - 1536) % 768];
    }
}

extern "C" void kernel_launch(void* const* d_in, const int* in_sizes, int n_in,
                              void* d_out, int out_size) {
    // order: fv, fv_alter, fi, dec (unused), ts, ode_w1, ode_b1, ode_w2, ode_b2,
    // reg_w1, reg_b1, reg_w2, reg_b2, reg_w3, reg_b3, reg_w4, reg_b4
    const float* ts  = (const float*)d_in[4];
    const float* w1  = (const float*)d_in[5];
    const float* b1  = (const float*)d_in[6];
    const float* w2  = (const float*)d_in[7];
    const float* b2  = (const float*)d_in[8];
    const float* rw1 = (const float*)d_in[9];
    const float* rb1 = (const float*)d_in[10];
    const float* rw2 = (const float*)d_in[11];
    const float* rb2 = (const float*)d_in[12];
    const float* rw3 = (const float*)d_in[13];
    const float* rb3 = (const float*)d_in[14];
    const float* rw4 = (const float*)d_in[15];
    const float* rb4 = (const float*)d_in[16];

    pose_ode_kernel<<<G, T>>>(ts, w1, b1, w2, b2,
                              rw1, rb1, rw2, rb2, rw3, rb3, rw4, rb4,
                              (float*)d_out, out_size);
}